// round 16
// baseline (speedup 1.0000x reference)
#include <cuda_runtime.h>
#include <cuda_bf16.h>
#include <cuda_fp16.h>
#include <math.h>
#include <stdint.h>

// Problem constants
#define KDIM   2048
#define KHD    128
#define KNH    16
#define KBATCH 2
#define KSEQ   2048
#define KQKV   6144
#define KMODEL 2048
#define KROWS  (KBATCH * KSEQ)   // 4096
#define K2     (2 * KDIM)        // 4096 : [hi | lo] / [hi | hi] fp16 split-K

// Scratch (device globals: allocation-free rule)
__device__ __align__(16) __half g_qkv16[(size_t)KROWS * KQKV];     // fp16 qkv for flash
__device__ __align__(16) __half g_x16[(size_t)KROWS * KDIM];       // fp16 x
__device__ __align__(16) __half g_wq16[(size_t)KQKV * KDIM];       // fp16 w_qkv
__device__ __align__(16) __half g_comb2[(size_t)KROWS * K2];       // [hi|lo] attn out
__device__ __align__(16) __half g_wout2[(size_t)KMODEL * K2];      // [hi|hi] w_out

// ---------------------------------------------------------------------------
// fp32 -> fp16 convert (contiguous)
// ---------------------------------------------------------------------------
__global__ __launch_bounds__(256) void conv_f16(
    const float* __restrict__ src, __half* __restrict__ dst, int total4)
{
    int idx = blockIdx.x * blockDim.x + threadIdx.x;
    if (idx >= total4) return;
    float4 v = *(const float4*)(src + (size_t)idx * 4);
    __half2 h0 = __floats2half2_rn(v.x, v.y);
    __half2 h1 = __floats2half2_rn(v.z, v.w);
    uint2 p;
    p.x = *(uint32_t*)&h0;
    p.y = *(uint32_t*)&h1;
    *(uint2*)(dst + (size_t)idx * 4) = p;
}

// ---------------------------------------------------------------------------
// fp32 -> fp16 duplicated K-concat: dst row = [h | h]  (B operand)
// ---------------------------------------------------------------------------
__global__ __launch_bounds__(256) void dup_f16(
    const float* __restrict__ src, __half* __restrict__ dst, int total4, int K)
{
    int idx = blockIdx.x * blockDim.x + threadIdx.x;
    if (idx >= total4) return;
    int e = idx * 4;
    int r = e / K;
    int k = e - r * K;
    float4 v = *(const float4*)(src + (size_t)e);
    __half2 h0 = __floats2half2_rn(v.x, v.y);
    __half2 h1 = __floats2half2_rn(v.z, v.w);
    uint2 p;
    p.x = *(uint32_t*)&h0;
    p.y = *(uint32_t*)&h1;
    size_t rb = (size_t)r * (2 * K) + k;
    *(uint2*)(dst + rb)     = p;
    *(uint2*)(dst + rb + K) = p;
}

// ---------------------------------------------------------------------------
// Common helpers
// ---------------------------------------------------------------------------
__device__ __forceinline__ uint32_t smem_u32(const void* p) {
    uint32_t a;
    asm("{ .reg .u64 t; cvta.to.shared.u64 t, %1; cvt.u32.u64 %0, t; }"
        : "=r"(a) : "l"(p));
    return a;
}
__device__ __forceinline__ uint32_t sw128(uint32_t o) { return o ^ ((o >> 3) & 0x70); }

__device__ __forceinline__ void ldsm_x4(uint32_t addr, uint32_t& r0, uint32_t& r1,
                                        uint32_t& r2, uint32_t& r3) {
    asm volatile("ldmatrix.sync.aligned.m8n8.x4.shared.b16 {%0,%1,%2,%3}, [%4];"
                 : "=r"(r0), "=r"(r1), "=r"(r2), "=r"(r3) : "r"(addr));
}
__device__ __forceinline__ void ldsm_x4t(uint32_t addr, uint32_t& r0, uint32_t& r1,
                                         uint32_t& r2, uint32_t& r3) {
    asm volatile("ldmatrix.sync.aligned.m8n8.x4.trans.shared.b16 {%0,%1,%2,%3}, [%4];"
                 : "=r"(r0), "=r"(r1), "=r"(r2), "=r"(r3) : "r"(addr));
}
__device__ __forceinline__ void mma_f16(float& c0, float& c1, float& c2, float& c3,
                                        uint32_t a0, uint32_t a1, uint32_t a2, uint32_t a3,
                                        uint32_t b0, uint32_t b1) {
    asm volatile(
        "mma.sync.aligned.m16n8k16.row.col.f32.f16.f16.f32 "
        "{%0,%1,%2,%3}, {%4,%5,%6,%7}, {%8,%9}, {%0,%1,%2,%3};"
        : "+f"(c0), "+f"(c1), "+f"(c2), "+f"(c3)
        : "r"(a0), "r"(a1), "r"(a2), "r"(a3), "r"(b0), "r"(b1));
}
__device__ __forceinline__ float ex2f(float x) {
    float y;
    asm("ex2.approx.ftz.f32 %0, %1;" : "=f"(y) : "f"(x));
    return y;
}
#define CPA16(dst, src) \
    asm volatile("cp.async.cg.shared.global [%0], [%1], 16;" :: "r"(dst), "l"(src) : "memory")

// ---------------------------------------------------------------------------
// HMMA fp16 GEMM: C = A[M,K] * B[N,K]^T.
// CTA 128x256, 8 warps (2x4), warp tile 64x64 -> 8 ldmatrix per 32 MMAs.
// BK=64, 3-stage cp.async multistage, SW128 smem, m16n8k16.
// Output fp32 (Cf) or fp16 (Ch).
// ---------------------------------------------------------------------------
#define BM 128
#define BN 256
#define BK 64
#define ATILE_BYTES 16384                    // 128 rows * 128B
#define BTILE_BYTES 32768                    // 256 rows * 128B
#define STAGE_BYTES (ATILE_BYTES + BTILE_BYTES)   // 49152
#define NSTAGE 3
#define GEMM_SMEM   (NSTAGE * STAGE_BYTES)   // 147456

__global__ __launch_bounds__(256, 1) void gemm_hmma(
    const uint16_t* __restrict__ A, const uint16_t* __restrict__ B,
    float* __restrict__ Cf, __half* __restrict__ Ch, int N, int K)
{
    extern __shared__ char smem[];
    const uint32_t sbase = smem_u32(smem);
    const int tid = threadIdx.x;
    const int wid = tid >> 5;
    const int lane = tid & 31;
    const int wm = wid >> 2;       // 0..1 : 64 rows each
    const int wn = wid & 3;        // 0..3 : 64 cols each
    const int bm = blockIdx.y * BM;
    const int bn = blockIdx.x * BN;
    const int nchunk = K / BK;
    const size_t rowB = (size_t)K * 2;

    auto load_chunk = [&](int c, int stage) {
        const uint32_t st = (uint32_t)stage * STAGE_BYTES;
        const char* Asrc = (const char*)(A + (size_t)bm * K) + (size_t)c * 128;
        const char* Bsrc = (const char*)(B + (size_t)bn * K) + (size_t)c * 128;
#pragma unroll
        for (int i = 0; i < 4; i++) {
            int u = i * 256 + tid;
            int row = u >> 3, ku = u & 7;
            uint32_t dst = sbase + st + sw128((uint32_t)(row * 128 + ku * 16));
            CPA16(dst, Asrc + (size_t)row * rowB + ku * 16);
        }
#pragma unroll
        for (int i = 0; i < 8; i++) {
            int u = i * 256 + tid;
            int row = u >> 3, ku = u & 7;
            uint32_t dst = sbase + st + ATILE_BYTES + sw128((uint32_t)(row * 128 + ku * 16));
            CPA16(dst, Bsrc + (size_t)row * rowB + ku * 16);
        }
        asm volatile("cp.async.commit_group;" ::: "memory");
    };

    float acc[4][8][4];
#pragma unroll
    for (int mt = 0; mt < 4; mt++)
#pragma unroll
        for (int nt = 0; nt < 8; nt++)
#pragma unroll
            for (int q = 0; q < 4; q++) acc[mt][nt][q] = 0.f;

    load_chunk(0, 0);
    load_chunk(1, 1);

    const int lrow = lane & 15;
    const int lsel = lane >> 4;
    int s_cur = 0;
    int s_nxt = 2;

#pragma unroll 1
    for (int c = 0; c < nchunk; c++) {
        if (c + 1 < nchunk) { asm volatile("cp.async.wait_group 1;" ::: "memory"); }
        else                { asm volatile("cp.async.wait_group 0;" ::: "memory"); }
        __syncthreads();

        if (c + 2 < nchunk) load_chunk(c + 2, s_nxt);

        const uint32_t ab = sbase + (uint32_t)s_cur * STAGE_BYTES;
        const uint32_t bb = ab + ATILE_BYTES;
        const int m0 = wm * 64;
        const int n0 = wn * 64;

#pragma unroll
        for (int ks = 0; ks < 4; ks++) {
            const int chk = 2 * ks + lsel;
            uint32_t a[4][4];
#pragma unroll
            for (int mt = 0; mt < 2; mt++) {
                // one ldmatrix per 16-row pair; 4 m16 tiles = 4 ldsm? use 4
            }
#pragma unroll
            for (int mt = 0; mt < 4; mt++) {
                int r = m0 + mt * 16 + lrow;
                ldsm_x4(ab + sw128((uint32_t)(r * 128 + chk * 16)),
                        a[mt][0], a[mt][1], a[mt][2], a[mt][3]);
            }
            uint32_t blo[8], bhi[8];
#pragma unroll
            for (int p = 0; p < 4; p++) {
                int r = n0 + p * 16 + lrow;
                uint32_t r0, r1, r2, r3;
                ldsm_x4(bb + sw128((uint32_t)(r * 128 + chk * 16)), r0, r1, r2, r3);
                blo[2 * p] = r0; blo[2 * p + 1] = r1;
                bhi[2 * p] = r2; bhi[2 * p + 1] = r3;
            }
#pragma unroll
            for (int mt = 0; mt < 4; mt++)
#pragma unroll
                for (int nt = 0; nt < 8; nt++)
                    mma_f16(acc[mt][nt][0], acc[mt][nt][1], acc[mt][nt][2], acc[mt][nt][3],
                            a[mt][0], a[mt][1], a[mt][2], a[mt][3], blo[nt], bhi[nt]);
        }

        s_cur = (s_cur == NSTAGE - 1) ? 0 : s_cur + 1;
        s_nxt = (s_nxt == NSTAGE - 1) ? 0 : s_nxt + 1;
    }

    const int mbase = bm + wm * 64 + (lane >> 2);
    const int nbase = bn + wn * 64 + 2 * (lane & 3);
    if (Ch) {
#pragma unroll
        for (int mt = 0; mt < 4; mt++)
#pragma unroll
            for (int nt = 0; nt < 8; nt++) {
                __half* p0 = Ch + (size_t)(mbase + mt * 16) * N + nbase + nt * 8;
                __half* p1 = Ch + (size_t)(mbase + mt * 16 + 8) * N + nbase + nt * 8;
                *(__half2*)p0 = __floats2half2_rn(acc[mt][nt][0], acc[mt][nt][1]);
                *(__half2*)p1 = __floats2half2_rn(acc[mt][nt][2], acc[mt][nt][3]);
            }
    } else {
#pragma unroll
        for (int mt = 0; mt < 4; mt++)
#pragma unroll
            for (int nt = 0; nt < 8; nt++) {
                float* p0 = Cf + (size_t)(mbase + mt * 16) * N + nbase + nt * 8;
                float* p1 = Cf + (size_t)(mbase + mt * 16 + 8) * N + nbase + nt * 8;
                *(float2*)p0 = make_float2(acc[mt][nt][0], acc[mt][nt][1]);
                *(float2*)p1 = make_float2(acc[mt][nt][2], acc[mt][nt][3]);
            }
    }
}

// ---------------------------------------------------------------------------
// Flash attention, fp16 HMMA + f16x2 exp2, online softmax (unchanged).
// Grid (S/128, H, B), 256 threads = 8 warps, warp = 16 q rows (FBQ=128).
// ---------------------------------------------------------------------------
#define FBQ 128
#define FBK 64
#define NKT (KSEQ / FBK)         // 32
#define FQ_OFF 0
#define FK_OFF 32768
#define FV_OFF 65536
#define FLASH_SMEM 98304

__global__ __launch_bounds__(256) void flash_f16()
{
    extern __shared__ char smem[];
    const uint32_t sbase = smem_u32(smem);
    const int tid = threadIdx.x;
    const int wid = tid >> 5;
    const int lane = tid & 31;
    const int qb = blockIdx.x;
    const int h  = blockIdx.y;
    const int b  = blockIdx.z;
    const int q0 = qb * FBQ;

    const char* qkvb = (const char*)g_qkv16;
    const size_t rowB = (size_t)KQKV * 2;

    {
        const size_t base = (size_t)(b * KSEQ + q0) * rowB + (size_t)h * 256;
#pragma unroll
        for (int i = 0; i < 8; i++) {
            int u = i * 256 + tid;
            int row = u >> 4, c16 = u & 15;
            uint32_t dst = sbase + FQ_OFF + (uint32_t)(c16 >> 3) * 16384
                         + sw128((uint32_t)(row * 128 + (c16 & 7) * 16));
            CPA16(dst, qkvb + base + (size_t)row * rowB + c16 * 16);
        }
    }
    auto load_kv = [&](int kb) {
        const uint32_t st = (uint32_t)(kb & 1) * 16384;
        const size_t kbase = (size_t)(b * KSEQ + kb * FBK) * rowB + (size_t)(KNH + h) * 256;
        const size_t vbase = (size_t)(b * KSEQ + kb * FBK) * rowB + (size_t)(2 * KNH + h) * 256;
#pragma unroll
        for (int i = 0; i < 4; i++) {
            int u = i * 256 + tid;
            int row = u >> 4, c16 = u & 15;
            uint32_t off = (uint32_t)(c16 >> 3) * 8192
                         + sw128((uint32_t)(row * 128 + (c16 & 7) * 16));
            CPA16(sbase + FK_OFF + st + off, qkvb + kbase + (size_t)row * rowB + c16 * 16);
        }
#pragma unroll
        for (int i = 0; i < 4; i++) {
            int u = i * 256 + tid;
            int row = u >> 4, c16 = u & 15;
            uint32_t off = (uint32_t)(c16 >> 3) * 8192
                         + sw128((uint32_t)(row * 128 + (c16 & 7) * 16));
            CPA16(sbase + FV_OFF + st + off, qkvb + vbase + (size_t)row * rowB + c16 * 16);
        }
        asm volatile("cp.async.commit_group;" ::: "memory");
    };

    load_kv(0);
    load_kv(1);

    float o[17][4];
#pragma unroll
    for (int t = 0; t < 17; t++)
#pragma unroll
        for (int q = 0; q < 4; q++) o[t][q] = 0.f;
    float m0 = -1e30f, m1 = -1e30f;

    const float sl2e = 1.4426950408889634f * 0.08838834764831845f;
    const int lrow = lane & 15;
    const int lsel = lane >> 4;
    const uint32_t ones_b = (lane < 4) ? 0x3C003C00u : 0u;

#pragma unroll 1
    for (int kb = 0; kb < NKT; kb++) {
        if (kb + 1 < NKT) { asm volatile("cp.async.wait_group 1;" ::: "memory"); }
        else              { asm volatile("cp.async.wait_group 0;" ::: "memory"); }
        __syncthreads();

        const uint32_t kbuf = sbase + FK_OFF + (uint32_t)(kb & 1) * 16384;
        const uint32_t vbuf = sbase + FV_OFF + (uint32_t)(kb & 1) * 16384;
        const uint32_t qbuf = sbase + FQ_OFF;

        float s[8][4];
#pragma unroll
        for (int nt = 0; nt < 8; nt++)
#pragma unroll
            for (int q = 0; q < 4; q++) s[nt][q] = 0.f;

#pragma unroll
        for (int ks = 0; ks < 8; ks++) {
            const uint32_t qchko = (uint32_t)(ks >> 2) * 16384;
            const uint32_t kchko = (uint32_t)(ks >> 2) * 8192;
            const int chk = 2 * (ks & 3) + lsel;
            uint32_t a0, a1, a2, a3;
            {
                int r = wid * 16 + lrow;
                ldsm_x4(qbuf + qchko + sw128((uint32_t)(r * 128 + chk * 16)), a0, a1, a2, a3);
            }
            uint32_t blo[8], bhi[8];
#pragma unroll
            for (int p = 0; p < 4; p++) {
                int r = p * 16 + lrow;
                uint32_t r0, r1, r2, r3;
                ldsm_x4(kbuf + kchko + sw128((uint32_t)(r * 128 + chk * 16)), r0, r1, r2, r3);
                blo[2 * p] = r0; blo[2 * p + 1] = r1;
                bhi[2 * p] = r2; bhi[2 * p + 1] = r3;
            }
#pragma unroll
            for (int nt = 0; nt < 8; nt++)
                mma_f16(s[nt][0], s[nt][1], s[nt][2], s[nt][3],
                        a0, a1, a2, a3, blo[nt], bhi[nt]);
        }

        float mx0 = -1e30f, mx1 = -1e30f;
#pragma unroll
        for (int nt = 0; nt < 8; nt++) {
            s[nt][0] *= sl2e; s[nt][1] *= sl2e;
            s[nt][2] *= sl2e; s[nt][3] *= sl2e;
            mx0 = fmaxf(mx0, fmaxf(s[nt][0], s[nt][1]));
            mx1 = fmaxf(mx1, fmaxf(s[nt][2], s[nt][3]));
        }
        mx0 = fmaxf(mx0, __shfl_xor_sync(0xffffffffu, mx0, 1));
        mx0 = fmaxf(mx0, __shfl_xor_sync(0xffffffffu, mx0, 2));
        mx1 = fmaxf(mx1, __shfl_xor_sync(0xffffffffu, mx1, 1));
        mx1 = fmaxf(mx1, __shfl_xor_sync(0xffffffffu, mx1, 2));
        const float mn0 = fmaxf(m0, mx0);
        const float mn1 = fmaxf(m1, mx1);
        const float corr0 = ex2f(m0 - mn0);
        const float corr1 = ex2f(m1 - mn1);
        m0 = mn0; m1 = mn1;
#pragma unroll
        for (int t = 0; t < 17; t++) {
            o[t][0] *= corr0; o[t][1] *= corr0;
            o[t][2] *= corr1; o[t][3] *= corr1;
        }
        uint32_t p01[8], p23[8];
#pragma unroll
        for (int nt = 0; nt < 8; nt++) {
            __half2 h0 = h2exp2(__floats2half2_rn(s[nt][0] - mn0, s[nt][1] - mn0));
            __half2 h1 = h2exp2(__floats2half2_rn(s[nt][2] - mn1, s[nt][3] - mn1));
            p01[nt] = *(uint32_t*)&h0;
            p23[nt] = *(uint32_t*)&h1;
        }

        const int grp  = lane >> 3;
        const int glr  = lane & 7;
#pragma unroll
        for (int ks = 0; ks < 4; ks++) {
            const uint32_t a0 = p01[2 * ks],     a1 = p23[2 * ks];
            const uint32_t a2 = p01[2 * ks + 1], a3 = p23[2 * ks + 1];
            const int key = 16 * ks + (grp & 1) * 8 + glr;
#pragma unroll
            for (int pp = 0; pp < 8; pp++) {
                const int d = pp * 16 + (grp >> 1) * 8;
                const uint32_t addr = vbuf + (uint32_t)(d >> 6) * 8192
                                    + sw128((uint32_t)(key * 128 + (d & 63) * 2));
                uint32_t r0, r1, r2, r3;
                ldsm_x4t(addr, r0, r1, r2, r3);
                mma_f16(o[2 * pp][0], o[2 * pp][1], o[2 * pp][2], o[2 * pp][3],
                        a0, a1, a2, a3, r0, r1);
                mma_f16(o[2 * pp + 1][0], o[2 * pp + 1][1], o[2 * pp + 1][2], o[2 * pp + 1][3],
                        a0, a1, a2, a3, r2, r3);
            }
            mma_f16(o[16][0], o[16][1], o[16][2], o[16][3],
                    a0, a1, a2, a3, ones_b, ones_b);
        }

        __syncthreads();
        if (kb + 2 < NKT) load_kv(kb + 2);
    }

    const int src = lane & ~3;
    const float l0 = __shfl_sync(0xffffffffu, o[16][0], src);
    const float l1 = __shfl_sync(0xffffffffu, o[16][2], src);
    const float inv0 = 1.f / l0;
    const float inv1 = 1.f / l1;

    const int gr0 = b * KSEQ + q0 + wid * 16 + (lane >> 2);
    const int col0 = h * KHD + 2 * (lane & 3);
#pragma unroll
    for (int t = 0; t < 16; t++) {
#pragma unroll
        for (int rr = 0; rr < 2; rr++) {
            float v0 = o[t][2 * rr + 0] * (rr ? inv1 : inv0);
            float v1 = o[t][2 * rr + 1] * (rr ? inv1 : inv0);
            __half h0 = __float2half_rn(v0);
            __half h1 = __float2half_rn(v1);
            __half l0h = __float2half_rn(v0 - __half2float(h0));
            __half l1h = __float2half_rn(v1 - __half2float(h1));
            uint32_t hp = (uint32_t)__half_as_ushort(h0)
                        | ((uint32_t)__half_as_ushort(h1) << 16);
            uint32_t lp = (uint32_t)__half_as_ushort(l0h)
                        | ((uint32_t)__half_as_ushort(l1h) << 16);
            __half* dst = g_comb2 + (size_t)(gr0 + rr * 8) * K2 + col0 + t * 8;
            *(uint32_t*)(dst)        = hp;
            *(uint32_t*)(dst + KDIM) = lp;
        }
    }
}

// ---------------------------------------------------------------------------
extern "C" void kernel_launch(void* const* d_in, const int* in_sizes, int n_in,
                              void* d_out, int out_size)
{
    (void)in_sizes; (void)n_in; (void)out_size;
    const float* x     = (const float*)d_in[0];
    const float* w_qkv = (const float*)d_in[1];
    const float* w_out = (const float*)d_in[2];
    float* out = (float*)d_out;

    __half* qkv16_p; cudaGetSymbolAddress((void**)&qkv16_p, g_qkv16);
    __half* x16_p;   cudaGetSymbolAddress((void**)&x16_p,   g_x16);
    __half* wq16_p;  cudaGetSymbolAddress((void**)&wq16_p,  g_wq16);
    __half* cb_p;    cudaGetSymbolAddress((void**)&cb_p,    g_comb2);
    __half* wo_p;    cudaGetSymbolAddress((void**)&wo_p,    g_wout2);

    // 0) Converts / dup
    {
        int t4;
        t4 = KROWS * KDIM / 4;
        conv_f16<<<(t4 + 255) / 256, 256>>>(x, x16_p, t4);
        t4 = KQKV * KDIM / 4;
        conv_f16<<<(t4 + 255) / 256, 256>>>(w_qkv, wq16_p, t4);
        t4 = KMODEL * KDIM / 4;
        dup_f16<<<(t4 + 255) / 256, 256>>>(w_out, wo_p, t4, KDIM);
    }

    cudaFuncSetAttribute(gemm_hmma,
                         cudaFuncAttributeMaxDynamicSharedMemorySize, GEMM_SMEM);

    // 1) QKV projection (fp16 HMMA, K=2048) -> fp16 g_qkv16
    {
        dim3 grid(KQKV / BN, KROWS / BM);
        gemm_hmma<<<grid, 256, GEMM_SMEM>>>(
            (const uint16_t*)x16_p, (const uint16_t*)wq16_p,
            nullptr, qkv16_p, KQKV, KDIM);
    }

    // 2) Flash attention (fp16 HMMA, FBQ=128) -> fp16 [hi|lo] g_comb2
    {
        cudaFuncSetAttribute(flash_f16,
                             cudaFuncAttributeMaxDynamicSharedMemorySize, FLASH_SMEM);
        dim3 grid(KSEQ / FBQ, KNH, KBATCH);
        flash_f16<<<grid, 256, FLASH_SMEM>>>();
    }

    // 3) Output projection (fp16 2-term split, K=4096) -> fp32 out
    {
        dim3 grid(KMODEL / BN, KROWS / BM);
        gemm_hmma<<<grid, 256, GEMM_SMEM>>>(
            (const uint16_t*)cb_p, (const uint16_t*)wo_p,
            out, nullptr, KMODEL, K2);
    }
}

// round 17
// speedup vs baseline: 1.2843x; 1.2843x over previous
#include <cuda_runtime.h>
#include <cuda_bf16.h>
#include <cuda_fp16.h>
#include <math.h>
#include <stdint.h>

// Problem constants
#define KDIM   2048
#define KHD    128
#define KNH    16
#define KBATCH 2
#define KSEQ   2048
#define KQKV   6144
#define KMODEL 2048
#define KROWS  (KBATCH * KSEQ)   // 4096

// Scratch (device globals: allocation-free rule)
__device__ __align__(16) __half g_qkv16[(size_t)KROWS * KQKV];     // fp16 qkv for flash
__device__ __align__(16) __half g_x16[(size_t)KROWS * KDIM];       // fp16 x
__device__ __align__(16) __half g_wq16[(size_t)KQKV * KDIM];       // fp16 w_qkv
__device__ __align__(16) __half g_comb16[(size_t)KROWS * KMODEL];  // fp16 attn out
__device__ __align__(16) __half g_wo16[(size_t)KMODEL * KDIM];     // fp16 w_out

// ---------------------------------------------------------------------------
// fp32 -> fp16 convert (contiguous)
// ---------------------------------------------------------------------------
__global__ __launch_bounds__(256) void conv_f16(
    const float* __restrict__ src, __half* __restrict__ dst, int total4)
{
    int idx = blockIdx.x * blockDim.x + threadIdx.x;
    if (idx >= total4) return;
    float4 v = *(const float4*)(src + (size_t)idx * 4);
    __half2 h0 = __floats2half2_rn(v.x, v.y);
    __half2 h1 = __floats2half2_rn(v.z, v.w);
    uint2 p;
    p.x = *(uint32_t*)&h0;
    p.y = *(uint32_t*)&h1;
    *(uint2*)(dst + (size_t)idx * 4) = p;
}

// ---------------------------------------------------------------------------
// Common helpers
// ---------------------------------------------------------------------------
__device__ __forceinline__ uint32_t smem_u32(const void* p) {
    uint32_t a;
    asm("{ .reg .u64 t; cvta.to.shared.u64 t, %1; cvt.u32.u64 %0, t; }"
        : "=r"(a) : "l"(p));
    return a;
}
__device__ __forceinline__ uint32_t sw128(uint32_t o) { return o ^ ((o >> 3) & 0x70); }

__device__ __forceinline__ void ldsm_x4(uint32_t addr, uint32_t& r0, uint32_t& r1,
                                        uint32_t& r2, uint32_t& r3) {
    asm volatile("ldmatrix.sync.aligned.m8n8.x4.shared.b16 {%0,%1,%2,%3}, [%4];"
                 : "=r"(r0), "=r"(r1), "=r"(r2), "=r"(r3) : "r"(addr));
}
__device__ __forceinline__ void ldsm_x4t(uint32_t addr, uint32_t& r0, uint32_t& r1,
                                         uint32_t& r2, uint32_t& r3) {
    asm volatile("ldmatrix.sync.aligned.m8n8.x4.trans.shared.b16 {%0,%1,%2,%3}, [%4];"
                 : "=r"(r0), "=r"(r1), "=r"(r2), "=r"(r3) : "r"(addr));
}
__device__ __forceinline__ void mma_f16(float& c0, float& c1, float& c2, float& c3,
                                        uint32_t a0, uint32_t a1, uint32_t a2, uint32_t a3,
                                        uint32_t b0, uint32_t b1) {
    asm volatile(
        "mma.sync.aligned.m16n8k16.row.col.f32.f16.f16.f32 "
        "{%0,%1,%2,%3}, {%4,%5,%6,%7}, {%8,%9}, {%0,%1,%2,%3};"
        : "+f"(c0), "+f"(c1), "+f"(c2), "+f"(c3)
        : "r"(a0), "r"(a1), "r"(a2), "r"(a3), "r"(b0), "r"(b1));
}
__device__ __forceinline__ float ex2f(float x) {
    float y;
    asm("ex2.approx.ftz.f32 %0, %1;" : "=f"(y) : "f"(x));
    return y;
}
#define CPA16(dst, src) \
    asm volatile("cp.async.cg.shared.global [%0], [%1], 16;" :: "r"(dst), "l"(src) : "memory")

// ---------------------------------------------------------------------------
// HMMA fp16 GEMM: C = A[M,K] * B[N,K]^T.   (R15 config — known best)
// CTA 128x128, 8 warps (4x2), warp tile 32x64, BK=64, 3-stage cp.async,
// SW128 smem, m16n8k16, 2 CTAs/SM. Output fp32 (Cf) or fp16 (Ch).
// ---------------------------------------------------------------------------
#define BM 128
#define BN 128
#define BK 64
#define TILE_BYTES 16384
#define STAGE_BYTES 32768
#define NSTAGE 3
#define GEMM_SMEM   (NSTAGE * STAGE_BYTES)   // 98304

__global__ __launch_bounds__(256, 2) void gemm_hmma(
    const uint16_t* __restrict__ A, const uint16_t* __restrict__ B,
    float* __restrict__ Cf, __half* __restrict__ Ch, int N, int K)
{
    extern __shared__ char smem[];
    const uint32_t sbase = smem_u32(smem);
    const int tid = threadIdx.x;
    const int wid = tid >> 5;
    const int lane = tid & 31;
    const int wm = wid >> 1;
    const int wn = wid & 1;
    const int bm = blockIdx.y * BM;
    const int bn = blockIdx.x * BN;
    const int nchunk = K / BK;
    const size_t rowB = (size_t)K * 2;

    auto load_chunk = [&](int c, int stage) {
        const uint32_t st = (uint32_t)stage * STAGE_BYTES;
        const char* Asrc = (const char*)(A + (size_t)bm * K) + (size_t)c * 128;
        const char* Bsrc = (const char*)(B + (size_t)bn * K) + (size_t)c * 128;
#pragma unroll
        for (int i = 0; i < 4; i++) {
            int u = i * 256 + tid;
            int row = u >> 3, ku = u & 7;
            uint32_t dst = sbase + st + sw128((uint32_t)(row * 128 + ku * 16));
            CPA16(dst, Asrc + (size_t)row * rowB + ku * 16);
        }
#pragma unroll
        for (int i = 0; i < 4; i++) {
            int u = i * 256 + tid;
            int row = u >> 3, ku = u & 7;
            uint32_t dst = sbase + st + TILE_BYTES + sw128((uint32_t)(row * 128 + ku * 16));
            CPA16(dst, Bsrc + (size_t)row * rowB + ku * 16);
        }
        asm volatile("cp.async.commit_group;" ::: "memory");
    };

    float acc[2][8][4];
#pragma unroll
    for (int mt = 0; mt < 2; mt++)
#pragma unroll
        for (int nt = 0; nt < 8; nt++)
#pragma unroll
            for (int q = 0; q < 4; q++) acc[mt][nt][q] = 0.f;

    load_chunk(0, 0);
    load_chunk(1, 1);

    const int lrow = lane & 15;
    const int lsel = lane >> 4;
    int s_cur = 0;
    int s_nxt = 2;

#pragma unroll 1
    for (int c = 0; c < nchunk; c++) {
        if (c + 1 < nchunk) { asm volatile("cp.async.wait_group 1;" ::: "memory"); }
        else                { asm volatile("cp.async.wait_group 0;" ::: "memory"); }
        __syncthreads();

        if (c + 2 < nchunk) load_chunk(c + 2, s_nxt);

        const uint32_t ab = sbase + (uint32_t)s_cur * STAGE_BYTES;
        const uint32_t bb = ab + TILE_BYTES;
        const int m0 = wm * 32;
        const int n0 = wn * 64;

#pragma unroll
        for (int ks = 0; ks < 4; ks++) {
            const int chk = 2 * ks + lsel;
            uint32_t a[2][4];
#pragma unroll
            for (int mt = 0; mt < 2; mt++) {
                int r = m0 + mt * 16 + lrow;
                ldsm_x4(ab + sw128((uint32_t)(r * 128 + chk * 16)),
                        a[mt][0], a[mt][1], a[mt][2], a[mt][3]);
            }
            uint32_t blo[8], bhi[8];
#pragma unroll
            for (int p = 0; p < 4; p++) {
                int r = n0 + p * 16 + lrow;
                uint32_t r0, r1, r2, r3;
                ldsm_x4(bb + sw128((uint32_t)(r * 128 + chk * 16)), r0, r1, r2, r3);
                blo[2 * p] = r0; blo[2 * p + 1] = r1;
                bhi[2 * p] = r2; bhi[2 * p + 1] = r3;
            }
#pragma unroll
            for (int mt = 0; mt < 2; mt++)
#pragma unroll
                for (int nt = 0; nt < 8; nt++)
                    mma_f16(acc[mt][nt][0], acc[mt][nt][1], acc[mt][nt][2], acc[mt][nt][3],
                            a[mt][0], a[mt][1], a[mt][2], a[mt][3], blo[nt], bhi[nt]);
        }

        s_cur = (s_cur == NSTAGE - 1) ? 0 : s_cur + 1;
        s_nxt = (s_nxt == NSTAGE - 1) ? 0 : s_nxt + 1;
    }

    const int mbase = bm + wm * 32 + (lane >> 2);
    const int nbase = bn + wn * 64 + 2 * (lane & 3);
    if (Ch) {
#pragma unroll
        for (int mt = 0; mt < 2; mt++)
#pragma unroll
            for (int nt = 0; nt < 8; nt++) {
                __half* p0 = Ch + (size_t)(mbase + mt * 16) * N + nbase + nt * 8;
                __half* p1 = Ch + (size_t)(mbase + mt * 16 + 8) * N + nbase + nt * 8;
                *(__half2*)p0 = __floats2half2_rn(acc[mt][nt][0], acc[mt][nt][1]);
                *(__half2*)p1 = __floats2half2_rn(acc[mt][nt][2], acc[mt][nt][3]);
            }
    } else {
#pragma unroll
        for (int mt = 0; mt < 2; mt++)
#pragma unroll
            for (int nt = 0; nt < 8; nt++) {
                float* p0 = Cf + (size_t)(mbase + mt * 16) * N + nbase + nt * 8;
                float* p1 = Cf + (size_t)(mbase + mt * 16 + 8) * N + nbase + nt * 8;
                *(float2*)p0 = make_float2(acc[mt][nt][0], acc[mt][nt][1]);
                *(float2*)p1 = make_float2(acc[mt][nt][2], acc[mt][nt][3]);
            }
    }
}

// ---------------------------------------------------------------------------
// Flash attention, fp16 HMMA + f16x2 exp2, online softmax.
// Grid (S/128, H, B), 256 threads = 8 warps, warp = 16 q rows (FBQ=128).
// Epilogue writes plain fp16 into g_comb16.
// ---------------------------------------------------------------------------
#define FBQ 128
#define FBK 64
#define NKT (KSEQ / FBK)         // 32
#define FQ_OFF 0
#define FK_OFF 32768
#define FV_OFF 65536
#define FLASH_SMEM 98304

__global__ __launch_bounds__(256) void flash_f16()
{
    extern __shared__ char smem[];
    const uint32_t sbase = smem_u32(smem);
    const int tid = threadIdx.x;
    const int wid = tid >> 5;
    const int lane = tid & 31;
    const int qb = blockIdx.x;
    const int h  = blockIdx.y;
    const int b  = blockIdx.z;
    const int q0 = qb * FBQ;

    const char* qkvb = (const char*)g_qkv16;
    const size_t rowB = (size_t)KQKV * 2;

    {
        const size_t base = (size_t)(b * KSEQ + q0) * rowB + (size_t)h * 256;
#pragma unroll
        for (int i = 0; i < 8; i++) {
            int u = i * 256 + tid;
            int row = u >> 4, c16 = u & 15;
            uint32_t dst = sbase + FQ_OFF + (uint32_t)(c16 >> 3) * 16384
                         + sw128((uint32_t)(row * 128 + (c16 & 7) * 16));
            CPA16(dst, qkvb + base + (size_t)row * rowB + c16 * 16);
        }
    }
    auto load_kv = [&](int kb) {
        const uint32_t st = (uint32_t)(kb & 1) * 16384;
        const size_t kbase = (size_t)(b * KSEQ + kb * FBK) * rowB + (size_t)(KNH + h) * 256;
        const size_t vbase = (size_t)(b * KSEQ + kb * FBK) * rowB + (size_t)(2 * KNH + h) * 256;
#pragma unroll
        for (int i = 0; i < 4; i++) {
            int u = i * 256 + tid;
            int row = u >> 4, c16 = u & 15;
            uint32_t off = (uint32_t)(c16 >> 3) * 8192
                         + sw128((uint32_t)(row * 128 + (c16 & 7) * 16));
            CPA16(sbase + FK_OFF + st + off, qkvb + kbase + (size_t)row * rowB + c16 * 16);
        }
#pragma unroll
        for (int i = 0; i < 4; i++) {
            int u = i * 256 + tid;
            int row = u >> 4, c16 = u & 15;
            uint32_t off = (uint32_t)(c16 >> 3) * 8192
                         + sw128((uint32_t)(row * 128 + (c16 & 7) * 16));
            CPA16(sbase + FV_OFF + st + off, qkvb + vbase + (size_t)row * rowB + c16 * 16);
        }
        asm volatile("cp.async.commit_group;" ::: "memory");
    };

    load_kv(0);
    load_kv(1);

    float o[17][4];
#pragma unroll
    for (int t = 0; t < 17; t++)
#pragma unroll
        for (int q = 0; q < 4; q++) o[t][q] = 0.f;
    float m0 = -1e30f, m1 = -1e30f;

    const float sl2e = 1.4426950408889634f * 0.08838834764831845f;
    const int lrow = lane & 15;
    const int lsel = lane >> 4;
    const uint32_t ones_b = (lane < 4) ? 0x3C003C00u : 0u;

#pragma unroll 1
    for (int kb = 0; kb < NKT; kb++) {
        if (kb + 1 < NKT) { asm volatile("cp.async.wait_group 1;" ::: "memory"); }
        else              { asm volatile("cp.async.wait_group 0;" ::: "memory"); }
        __syncthreads();

        const uint32_t kbuf = sbase + FK_OFF + (uint32_t)(kb & 1) * 16384;
        const uint32_t vbuf = sbase + FV_OFF + (uint32_t)(kb & 1) * 16384;
        const uint32_t qbuf = sbase + FQ_OFF;

        float s[8][4];
#pragma unroll
        for (int nt = 0; nt < 8; nt++)
#pragma unroll
            for (int q = 0; q < 4; q++) s[nt][q] = 0.f;

#pragma unroll
        for (int ks = 0; ks < 8; ks++) {
            const uint32_t qchko = (uint32_t)(ks >> 2) * 16384;
            const uint32_t kchko = (uint32_t)(ks >> 2) * 8192;
            const int chk = 2 * (ks & 3) + lsel;
            uint32_t a0, a1, a2, a3;
            {
                int r = wid * 16 + lrow;
                ldsm_x4(qbuf + qchko + sw128((uint32_t)(r * 128 + chk * 16)), a0, a1, a2, a3);
            }
            uint32_t blo[8], bhi[8];
#pragma unroll
            for (int p = 0; p < 4; p++) {
                int r = p * 16 + lrow;
                uint32_t r0, r1, r2, r3;
                ldsm_x4(kbuf + kchko + sw128((uint32_t)(r * 128 + chk * 16)), r0, r1, r2, r3);
                blo[2 * p] = r0; blo[2 * p + 1] = r1;
                bhi[2 * p] = r2; bhi[2 * p + 1] = r3;
            }
#pragma unroll
            for (int nt = 0; nt < 8; nt++)
                mma_f16(s[nt][0], s[nt][1], s[nt][2], s[nt][3],
                        a0, a1, a2, a3, blo[nt], bhi[nt]);
        }

        float mx0 = -1e30f, mx1 = -1e30f;
#pragma unroll
        for (int nt = 0; nt < 8; nt++) {
            s[nt][0] *= sl2e; s[nt][1] *= sl2e;
            s[nt][2] *= sl2e; s[nt][3] *= sl2e;
            mx0 = fmaxf(mx0, fmaxf(s[nt][0], s[nt][1]));
            mx1 = fmaxf(mx1, fmaxf(s[nt][2], s[nt][3]));
        }
        mx0 = fmaxf(mx0, __shfl_xor_sync(0xffffffffu, mx0, 1));
        mx0 = fmaxf(mx0, __shfl_xor_sync(0xffffffffu, mx0, 2));
        mx1 = fmaxf(mx1, __shfl_xor_sync(0xffffffffu, mx1, 1));
        mx1 = fmaxf(mx1, __shfl_xor_sync(0xffffffffu, mx1, 2));
        const float mn0 = fmaxf(m0, mx0);
        const float mn1 = fmaxf(m1, mx1);
        const float corr0 = ex2f(m0 - mn0);
        const float corr1 = ex2f(m1 - mn1);
        m0 = mn0; m1 = mn1;
#pragma unroll
        for (int t = 0; t < 17; t++) {
            o[t][0] *= corr0; o[t][1] *= corr0;
            o[t][2] *= corr1; o[t][3] *= corr1;
        }
        uint32_t p01[8], p23[8];
#pragma unroll
        for (int nt = 0; nt < 8; nt++) {
            __half2 h0 = h2exp2(__floats2half2_rn(s[nt][0] - mn0, s[nt][1] - mn0));
            __half2 h1 = h2exp2(__floats2half2_rn(s[nt][2] - mn1, s[nt][3] - mn1));
            p01[nt] = *(uint32_t*)&h0;
            p23[nt] = *(uint32_t*)&h1;
        }

        const int grp  = lane >> 3;
        const int glr  = lane & 7;
#pragma unroll
        for (int ks = 0; ks < 4; ks++) {
            const uint32_t a0 = p01[2 * ks],     a1 = p23[2 * ks];
            const uint32_t a2 = p01[2 * ks + 1], a3 = p23[2 * ks + 1];
            const int key = 16 * ks + (grp & 1) * 8 + glr;
#pragma unroll
            for (int pp = 0; pp < 8; pp++) {
                const int d = pp * 16 + (grp >> 1) * 8;
                const uint32_t addr = vbuf + (uint32_t)(d >> 6) * 8192
                                    + sw128((uint32_t)(key * 128 + (d & 63) * 2));
                uint32_t r0, r1, r2, r3;
                ldsm_x4t(addr, r0, r1, r2, r3);
                mma_f16(o[2 * pp][0], o[2 * pp][1], o[2 * pp][2], o[2 * pp][3],
                        a0, a1, a2, a3, r0, r1);
                mma_f16(o[2 * pp + 1][0], o[2 * pp + 1][1], o[2 * pp + 1][2], o[2 * pp + 1][3],
                        a0, a1, a2, a3, r2, r3);
            }
            mma_f16(o[16][0], o[16][1], o[16][2], o[16][3],
                    a0, a1, a2, a3, ones_b, ones_b);
        }

        __syncthreads();
        if (kb + 2 < NKT) load_kv(kb + 2);
    }

    // ---- Epilogue: normalize, write plain fp16 into g_comb16 ----
    const int src = lane & ~3;
    const float l0 = __shfl_sync(0xffffffffu, o[16][0], src);
    const float l1 = __shfl_sync(0xffffffffu, o[16][2], src);
    const float inv0 = 1.f / l0;
    const float inv1 = 1.f / l1;

    const int gr0 = b * KSEQ + q0 + wid * 16 + (lane >> 2);
    const int col0 = h * KHD + 2 * (lane & 3);
#pragma unroll
    for (int t = 0; t < 16; t++) {
#pragma unroll
        for (int rr = 0; rr < 2; rr++) {
            float v0 = o[t][2 * rr + 0] * (rr ? inv1 : inv0);
            float v1 = o[t][2 * rr + 1] * (rr ? inv1 : inv0);
            __half2 hp = __floats2half2_rn(v0, v1);
            __half* dst = g_comb16 + (size_t)(gr0 + rr * 8) * KMODEL + col0 + t * 8;
            *(uint32_t*)dst = *(uint32_t*)&hp;
        }
    }
}

// ---------------------------------------------------------------------------
extern "C" void kernel_launch(void* const* d_in, const int* in_sizes, int n_in,
                              void* d_out, int out_size)
{
    (void)in_sizes; (void)n_in; (void)out_size;
    const float* x     = (const float*)d_in[0];
    const float* w_qkv = (const float*)d_in[1];
    const float* w_out = (const float*)d_in[2];
    float* out = (float*)d_out;

    __half* qkv16_p; cudaGetSymbolAddress((void**)&qkv16_p, g_qkv16);
    __half* x16_p;   cudaGetSymbolAddress((void**)&x16_p,   g_x16);
    __half* wq16_p;  cudaGetSymbolAddress((void**)&wq16_p,  g_wq16);
    __half* cb_p;    cudaGetSymbolAddress((void**)&cb_p,    g_comb16);
    __half* wo_p;    cudaGetSymbolAddress((void**)&wo_p,    g_wo16);

    // 0) Converts
    {
        int t4;
        t4 = KROWS * KDIM / 4;
        conv_f16<<<(t4 + 255) / 256, 256>>>(x, x16_p, t4);
        t4 = KQKV * KDIM / 4;
        conv_f16<<<(t4 + 255) / 256, 256>>>(w_qkv, wq16_p, t4);
        t4 = KMODEL * KDIM / 4;
        conv_f16<<<(t4 + 255) / 256, 256>>>(w_out, wo_p, t4);
    }

    cudaFuncSetAttribute(gemm_hmma,
                         cudaFuncAttributeMaxDynamicSharedMemorySize, GEMM_SMEM);

    // 1) QKV projection (fp16 HMMA, K=2048) -> fp16 g_qkv16
    {
        dim3 grid(KQKV / BN, KROWS / BM);
        gemm_hmma<<<grid, 256, GEMM_SMEM>>>(
            (const uint16_t*)x16_p, (const uint16_t*)wq16_p,
            nullptr, qkv16_p, KQKV, KDIM);
    }

    // 2) Flash attention (fp16 HMMA, FBQ=128) -> fp16 g_comb16
    {
        cudaFuncSetAttribute(flash_f16,
                             cudaFuncAttributeMaxDynamicSharedMemorySize, FLASH_SMEM);
        dim3 grid(KSEQ / FBQ, KNH, KBATCH);
        flash_f16<<<grid, 256, FLASH_SMEM>>>();
    }

    // 3) Output projection (plain fp16 HMMA, K=2048) -> fp32 out
    {
        dim3 grid(KMODEL / BN, KROWS / BM);
        gemm_hmma<<<grid, 256, GEMM_SMEM>>>(
            (const uint16_t*)cb_p, (const uint16_t*)wo_p,
            out, nullptr, KMODEL, KDIM);
    }
}